// round 4
// baseline (speedup 1.0000x reference)
#include <cuda_runtime.h>
#include <cstdint>
#include <cstddef>

// Problem constants
#define T_TOKENS 65536
#define DM 2048
#define NE 64

// Tiling
#define TILE_T 128      // tokens per CTA
#define KC 32           // K-chunk
#define THREADS 256     // 16 expert-groups (tx) x 16 token-groups (ty)

// Output layout (flattened tuple, all float32):
//   [0, T*E)            one-hot expert indices (0.0 / 1.0)
//   [T*E, T*E+T)        top_prob
//   [T*E+T, T*E+T+T*E)  logits
#define TP_OFF ((size_t)T_TOKENS * NE)
#define LG_OFF ((size_t)T_TOKENS * NE + T_TOKENS)

// ---- packed f32x2 helpers (sm_103a; ptxas will not auto-fuse these) ----
__device__ __forceinline__ unsigned long long fma2(unsigned long long a,
                                                   unsigned long long b,
                                                   unsigned long long c) {
    unsigned long long d;
    asm("fma.rn.f32x2 %0, %1, %2, %3;" : "=l"(d) : "l"(a), "l"(b), "l"(c));
    return d;
}
__device__ __forceinline__ unsigned long long dup2(float w) {
    unsigned long long d;
    asm("mov.b64 %0, {%1, %1};" : "=l"(d) : "f"(w));
    return d;
}
__device__ __forceinline__ float2 unpack2(unsigned long long u) {
    float2 f;
    asm("mov.b64 {%0, %1}, %2;" : "=f"(f.x), "=f"(f.y) : "l"(u));
    return f;
}

__global__ void __launch_bounds__(THREADS, 3)
router_kernel(const float* __restrict__ x,
              const float* __restrict__ W,
              float* __restrict__ out) {
    __shared__ __align__(16) float xs[KC][TILE_T];  // 16 KB, [k][token]
    __shared__ __align__(16) float ws[KC][NE];      //  8 KB, [k][expert]

    const int tid = threadIdx.x;
    const int tx = tid & 15;   // expert group: experts tx*4 .. tx*4+3
    const int ty = tid >> 4;   // token group:  tokens ty*8 .. ty*8+7
    const int t0 = blockIdx.x * TILE_T;

    // accumulators: acc[pair i][expert j], pair i = tokens (ty*8+2i, ty*8+2i+1)
    unsigned long long acc[4][4];
#pragma unroll
    for (int i = 0; i < 4; i++)
#pragma unroll
        for (int j = 0; j < 4; j++) acc[i][j] = 0ull;

    // tile-load index assignments
    const int xt = tid >> 1;            // token 0..127
    const int xk = (tid & 1) * 16;      // k sub-offset 0/16
    const int we = tid & 63;            // expert row 0..63
    const int wk = (tid >> 6) * 8;      // k sub-offset 0/8/16/24

    const float* xrow = x + (size_t)(t0 + xt) * DM + xk;
    const float* wrow = W + (size_t)we * DM + wk;

    for (int k0 = 0; k0 < DM; k0 += KC) {
        __syncthreads();  // previous chunk's compute done before overwrite

        // x tile: coalesced 16B loads, transpose into xs[k][t]
#pragma unroll
        for (int q = 0; q < 4; q++) {
            float4 v = *(const float4*)(xrow + k0 + q * 4);
            xs[xk + q * 4 + 0][xt] = v.x;
            xs[xk + q * 4 + 1][xt] = v.y;
            xs[xk + q * 4 + 2][xt] = v.z;
            xs[xk + q * 4 + 3][xt] = v.w;
        }
        // W tile: ws[k][e]; warp lanes span e=0..31/32..63 -> conflict-free STS
#pragma unroll
        for (int q = 0; q < 2; q++) {
            float4 v = *(const float4*)(wrow + k0 + q * 4);
            ws[wk + q * 4 + 0][we] = v.x;
            ws[wk + q * 4 + 1][we] = v.y;
            ws[wk + q * 4 + 2][we] = v.z;
            ws[wk + q * 4 + 3][we] = v.w;
        }
        __syncthreads();

#pragma unroll
        for (int k = 0; k < KC; k++) {
            // 8 tokens as 4 packed pairs (LDS.128 x2, broadcast across tx lanes)
            ulonglong2 xa = *(const ulonglong2*)&xs[k][ty * 8];
            ulonglong2 xb = *(const ulonglong2*)&xs[k][ty * 8 + 4];
            // 4 expert weights (LDS.128, conflict-free across tx lanes)
            float4 wf = *(const float4*)&ws[k][tx * 4];
            unsigned long long w0 = dup2(wf.x), w1 = dup2(wf.y),
                               w2 = dup2(wf.z), w3 = dup2(wf.w);

            acc[0][0] = fma2(xa.x, w0, acc[0][0]);
            acc[0][1] = fma2(xa.x, w1, acc[0][1]);
            acc[0][2] = fma2(xa.x, w2, acc[0][2]);
            acc[0][3] = fma2(xa.x, w3, acc[0][3]);
            acc[1][0] = fma2(xa.y, w0, acc[1][0]);
            acc[1][1] = fma2(xa.y, w1, acc[1][1]);
            acc[1][2] = fma2(xa.y, w2, acc[1][2]);
            acc[1][3] = fma2(xa.y, w3, acc[1][3]);
            acc[2][0] = fma2(xb.x, w0, acc[2][0]);
            acc[2][1] = fma2(xb.x, w1, acc[2][1]);
            acc[2][2] = fma2(xb.x, w2, acc[2][2]);
            acc[2][3] = fma2(xb.x, w3, acc[2][3]);
            acc[3][0] = fma2(xb.y, w0, acc[3][0]);
            acc[3][1] = fma2(xb.y, w1, acc[3][1]);
            acc[3][2] = fma2(xb.y, w2, acc[3][2]);
            acc[3][3] = fma2(xb.y, w3, acc[3][3]);
        }
    }

    // ---- epilogue: per-token softmax / argmax over the 16 tx lanes ----
    // Token t's 64 logits live on 16 consecutive lanes (same ty) -> shfl_xor.
#pragma unroll
    for (int i = 0; i < 4; i++) {
        float2 a0 = unpack2(acc[i][0]);
        float2 a1 = unpack2(acc[i][1]);
        float2 a2 = unpack2(acc[i][2]);
        float2 a3 = unpack2(acc[i][3]);

        // local argmax over this thread's 4 experts (prefer lower index on tie)
        float mx = a0.x; int ax = tx * 4;
        float my = a0.y; int ay = tx * 4;
        if (a1.x > mx) { mx = a1.x; ax = tx * 4 + 1; }
        if (a2.x > mx) { mx = a2.x; ax = tx * 4 + 2; }
        if (a3.x > mx) { mx = a3.x; ax = tx * 4 + 3; }
        if (a1.y > my) { my = a1.y; ay = tx * 4 + 1; }
        if (a2.y > my) { my = a2.y; ay = tx * 4 + 2; }
        if (a3.y > my) { my = a3.y; ay = tx * 4 + 3; }

        // butterfly max+argmax over the 16-lane group
#pragma unroll
        for (int mask = 1; mask < 16; mask <<= 1) {
            float omx = __shfl_xor_sync(0xffffffffu, mx, mask);
            int   oax = __shfl_xor_sync(0xffffffffu, ax, mask);
            float omy = __shfl_xor_sync(0xffffffffu, my, mask);
            int   oay = __shfl_xor_sync(0xffffffffu, ay, mask);
            if (omx > mx || (omx == mx && oax < ax)) { mx = omx; ax = oax; }
            if (omy > my || (omy == my && oay < ay)) { my = omy; ay = oay; }
        }

        // sum of exp(l - max) over 64 experts
        float sx = __expf(a0.x - mx) + __expf(a1.x - mx) +
                   __expf(a2.x - mx) + __expf(a3.x - mx);
        float sy = __expf(a0.y - my) + __expf(a1.y - my) +
                   __expf(a2.y - my) + __expf(a3.y - my);
#pragma unroll
        for (int mask = 1; mask < 16; mask <<= 1) {
            sx += __shfl_xor_sync(0xffffffffu, sx, mask);
            sy += __shfl_xor_sync(0xffffffffu, sy, mask);
        }

        const int tA = t0 + ty * 8 + 2 * i;      // even token of the pair
        const int tB = tA + 1;

        // logits (float4, lanes tx=0..15 cover the 64-expert row contiguously)
        float4 lgA = make_float4(a0.x, a1.x, a2.x, a3.x);
        float4 lgB = make_float4(a0.y, a1.y, a2.y, a3.y);
        *(float4*)(out + LG_OFF + (size_t)tA * NE + tx * 4) = lgA;
        *(float4*)(out + LG_OFF + (size_t)tB * NE + tx * 4) = lgB;

        // one-hot expert indices as 0.0/1.0
        float4 ohA = make_float4(tx * 4 + 0 == ax ? 1.f : 0.f,
                                 tx * 4 + 1 == ax ? 1.f : 0.f,
                                 tx * 4 + 2 == ax ? 1.f : 0.f,
                                 tx * 4 + 3 == ax ? 1.f : 0.f);
        float4 ohB = make_float4(tx * 4 + 0 == ay ? 1.f : 0.f,
                                 tx * 4 + 1 == ay ? 1.f : 0.f,
                                 tx * 4 + 2 == ay ? 1.f : 0.f,
                                 tx * 4 + 3 == ay ? 1.f : 0.f);
        *(float4*)(out + (size_t)tA * NE + tx * 4) = ohA;
        *(float4*)(out + (size_t)tB * NE + tx * 4) = ohB;

        // top_prob = exp(max - max) / sum = 1 / sum
        if (tx == 0) {
            out[TP_OFF + tA] = 1.0f / sx;
            out[TP_OFF + tB] = 1.0f / sy;
        }
    }
}

extern "C" void kernel_launch(void* const* d_in, const int* in_sizes, int n_in,
                              void* d_out, int out_size) {
    const float* x = (const float*)d_in[0];   // [65536, 2048] f32
    const float* W = (const float*)d_in[1];   // [64, 2048] f32
    float* out = (float*)d_out;

    dim3 grid(T_TOKENS / TILE_T);  // 512 CTAs
    dim3 block(THREADS);
    router_kernel<<<grid, block>>>(x, W, out);
}